// round 16
// baseline (speedup 1.0000x reference)
#include <cuda_runtime.h>
#include <cuda_bf16.h>
#include <math.h>
#include <stdint.h>

// ---------------- problem constants ----------------
namespace {
constexpr int B = 2, S = 2048, D = 1024, E = 16, HD = 64, CAP = 1280, TOPK = 8;
constexpr float EPS = 1e-6f;
constexpr int EB = E * B;    // 32
constexpr int NTOK = B * S;  // 4096
constexpr int MAXPOS = 2048;
}

// ---------------- scratch (device globals; no allocation allowed) ----------------
__device__ float g_route[NTOK * E];
__device__ float g_routeT[EB * S];
__device__ float g_wgt[E * D];
__device__ unsigned char g_mask[EB * S];
__device__ int   g_cnt[EB * 8];
__device__ float2 g_rope[MAXPOS * 32];
__device__ int   g_seq[EB * CAP];
__device__ float g_w[EB * CAP];
__device__ int   g_inv[E * NTOK];
__device__ uint32_t g_xh[NTOK * 512];
__device__ uint32_t g_wt[(size_t)E * 192 * 512];
__device__ uint32_t g_wfft[(size_t)E * 1024 * 32];
__device__ uint32_t g_qh[EB * CAP * 32];
__device__ uint32_t g_kh[EB * CAP * 32];
__device__ __nv_bfloat16 g_vt[(size_t)EB * HD * CAP];
__device__ uint32_t g_ctxh[EB * CAP * 32];
__device__ float g_opart[2 * EB * CAP * HD];
__device__ float g_pm[2 * EB * CAP];
__device__ float g_pl[2 * EB * CAP];
__device__ __nv_bfloat16 g_out[(size_t)EB * CAP * D];

// ---------------- helpers ----------------
__device__ __forceinline__ void mma_bf16(float& c0, float& c1, float& c2, float& c3,
                                         uint32_t a0, uint32_t a1, uint32_t a2, uint32_t a3,
                                         uint32_t b0, uint32_t b1) {
    asm volatile(
        "mma.sync.aligned.m16n8k16.row.col.f32.bf16.bf16.f32 "
        "{%0,%1,%2,%3}, {%4,%5,%6,%7}, {%8,%9}, {%0,%1,%2,%3};\n"
        : "+f"(c0), "+f"(c1), "+f"(c2), "+f"(c3)
        : "r"(a0), "r"(a1), "r"(a2), "r"(a3), "r"(b0), "r"(b1));
}
__device__ __forceinline__ uint32_t packbf(float a, float b) {
    __nv_bfloat162 t = __floats2bfloat162_rn(a, b);
    return *reinterpret_cast<uint32_t*>(&t);
}
__device__ __forceinline__ void cp_async16(uint32_t saddr, const void* g) {
    asm volatile("cp.async.ca.shared.global [%0], [%1], 16;" :: "r"(saddr), "l"(g));
}
__device__ __forceinline__ void cp_commit() { asm volatile("cp.async.commit_group;"); }
__device__ __forceinline__ void cp_wait0()  { asm volatile("cp.async.wait_group 0;"); }
__device__ __forceinline__ void cp_wait1()  { asm volatile("cp.async.wait_group 1;"); }

// ================= prep: transpose gate weights =================
__global__ void wgt_kernel(const float* __restrict__ wg) {
    int idx = blockIdx.x * 256 + threadIdx.x;
    int d = idx >> 4, e = idx & 15;
    g_wgt[e * D + d] = wg[idx];
}

// ================= fat front-end: gate | xpack | wt | wff | rope-table =================
__global__ void __launch_bounds__(256) fat_kernel(const float* __restrict__ x,
                                                  const float* __restrict__ bg,
                                                  const float* __restrict__ Wq,
                                                  const float* __restrict__ Wkv,
                                                  const float* __restrict__ Wff) {
    __shared__ float sm[64][65];
    int bx = blockIdx.x;
    int tid = threadIdx.x;

    if (bx < 512) {
        int warp = tid >> 5;
        int lane = tid & 31;
        int token = bx * 8 + warp;
        const float4* xr = (const float4*)(x + (size_t)token * D);
        float acc[E];
#pragma unroll
        for (int e = 0; e < E; e++) acc[e] = 0.f;
#pragma unroll
        for (int it = 0; it < 8; it++) {
            float4 xv = xr[lane + it * 32];
#pragma unroll
            for (int e = 0; e < E; e++) {
                float4 wv = *(const float4*)(g_wgt + e * D + (lane + it * 32) * 4);
                acc[e] += xv.x * wv.x + xv.y * wv.y + xv.z * wv.z + xv.w * wv.w;
            }
        }
#pragma unroll
        for (int off = 16; off; off >>= 1) {
#pragma unroll
            for (int e = 0; e < E; e++)
                acc[e] += __shfl_xor_sync(0xffffffffu, acc[e], off);
        }
        if (lane == 0) {
            float g[E];
            float mx = -3.402823466e38f;
#pragma unroll
            for (int e = 0; e < E; e++) {
                g[e] = acc[e] + bg[e];
                mx = fmaxf(mx, g[e]);
            }
            float den = 0.f;
#pragma unroll
            for (int e = 0; e < E; e++) { g[e] = expf(g[e] - mx); den += g[e]; }
            float inv = 1.f / den;
#pragma unroll
            for (int e = 0; e < E; e++) g[e] *= inv;
#pragma unroll
            for (int e = 0; e < E; e++) {
                int r = 0;
#pragma unroll
                for (int j = 0; j < E; j++)
                    r += (g[j] > g[e]) || (g[j] == g[e] && j < e);
                g_route[(size_t)token * E + e] = (r < TOPK) ? g[e] : 0.f;
            }
        }
    } else if (bx < 2560) {
        int idx = (bx - 512) * 256 + tid;
        const float4* src = (const float4*)x + (size_t)idx * 2;
        float4 v0 = src[0];
        float4 v1 = src[1];
        uint4 o;
        o.x = packbf(v0.x, v0.y);
        o.y = packbf(v0.z, v0.w);
        o.z = packbf(v1.x, v1.y);
        o.w = packbf(v1.z, v1.w);
        *((uint4*)g_xh + idx) = o;
    } else if (bx < 3328) {
        int i = bx - 2560;
        int e = i / 48;
        int rem = i % 48;
        int k0 = (rem / 3) * 64;
        int nz = rem % 3;
        int n0 = nz * 64;
        const float* src;
        int stride;
        if (nz == 0) { src = Wq + (size_t)e * D * HD; stride = HD; }
        else         { src = Wkv + (size_t)e * D * 128 + (n0 - 64); stride = 128; }
#pragma unroll
        for (int it = 0; it < 16; it++) {
            int idx = tid + it * 256;
            int kk = idx >> 6, nn = idx & 63;
            sm[kk][nn] = src[(size_t)(k0 + kk) * stride + nn];
        }
        __syncthreads();
#pragma unroll
        for (int it = 0; it < 8; it++) {
            int idx = tid + it * 256;
            int n = idx >> 5, kp = idx & 31;
            g_wt[((size_t)(e * 192 + n0 + n)) * 512 + (k0 >> 1) + kp] =
                packbf(sm[2 * kp][n], sm[2 * kp + 1][n]);
        }
    } else if (bx < 3584) {
        int i = bx - 3328;
        int e = i >> 4;
        int n0 = (i & 15) * 64;
#pragma unroll
        for (int it = 0; it < 16; it++) {
            int idx = tid + it * 256;
            int kk = idx >> 6, nn = idx & 63;
            sm[kk][nn] = Wff[(size_t)e * HD * D + (size_t)kk * D + n0 + nn];
        }
        __syncthreads();
#pragma unroll
        for (int it = 0; it < 8; it++) {
            int idx = tid + it * 256;
            int n = idx >> 5, kp = idx & 31;
            g_wfft[((size_t)(e * 1024 + n0 + n)) * 32 + kp] =
                packbf(sm[2 * kp][n], sm[2 * kp + 1][n]);
        }
    } else {
        int idx = (bx - 3584) * 256 + tid;
        int pos = idx >> 5, h = idx & 31;
        float invf = exp2f(-(float)h * 0.4152410118609203f);
        float sv, cv;
        sincosf((float)pos * invf, &sv, &cv);
        g_rope[idx] = make_float2(cv, sv);
    }
}

// ================= stage 3a: normalize + rank mask + counts + g_inv init =================
__global__ void mask_kernel() {
    int eb = blockIdx.x;
    int e = eb >> 1, b = eb & 1;
    __shared__ float sv[S];
    int tid = threadIdx.x;
    for (int s = tid; s < S; s += 256) {
        float m0 = g_route[(size_t)s * E + e];
        float m1 = g_route[(size_t)(S + s) * E + e];
        float den = m0 + m1 + EPS;
        sv[s] = (b ? m1 : m0) / den * 2.0f;
    }
    __syncthreads();
    if (blockIdx.y == 0) {
        for (int s = tid; s < S; s += 256)
            g_routeT[eb * S + s] = sv[s];
    }
    int i = blockIdx.y * 256 + tid;
    float vi = sv[i];
    int c = 0;
#pragma unroll 4
    for (int j4 = 0; j4 < S / 4; j4++) {
        float4 v = *(const float4*)(sv + j4 * 4);
        int j = j4 * 4;
        c += (v.x > vi) || (v.x == vi && (j + 0) < i);
        c += (v.y > vi) || (v.y == vi && (j + 1) < i);
        c += (v.z > vi) || (v.z == vi && (j + 2) < i);
        c += (v.w > vi) || (v.w == vi && (j + 3) < i);
    }
    int sel = (c < CAP) ? 1 : 0;
    g_mask[eb * S + i] = (unsigned char)sel;
    g_inv[e * NTOK + b * S + i] = -1;
    int total = __syncthreads_count(sel);
    if (tid == 0) g_cnt[eb * 8 + blockIdx.y] = total;
}

// ================= stage 3b: compaction =================
__global__ void select_kernel() {
    int eb = blockIdx.x, y = blockIdx.y;
    int e = eb >> 1, b = eb & 1;
    __shared__ int wsum[8];
    int t = threadIdx.x;
    int base = 0;
#pragma unroll
    for (int yy = 0; yy < 8; yy++)
        if (yy < y) base += g_cnt[eb * 8 + yy];
    int i = y * 256 + t;
    int sel = g_mask[eb * S + i];
    int lane = t & 31, warp = t >> 5;
    int scan = sel;
#pragma unroll
    for (int off = 1; off < 32; off <<= 1) {
        int v = __shfl_up_sync(0xffffffffu, scan, off);
        if (lane >= off) scan += v;
    }
    if (lane == 31) wsum[warp] = scan;
    __syncthreads();
#pragma unroll
    for (int wi = 0; wi < 8; wi++)
        if (wi < warp) base += wsum[wi];
    if (sel) {
        int pos = base + scan - sel;
        g_seq[eb * CAP + pos] = i;
        g_w[eb * CAP + pos] = g_routeT[eb * S + i];
        g_inv[e * NTOK + b * S + i] = pos;
    }
}

// ================= stage 4a: fused Q/K/V projection, BF16 mma, M=128 tile =========
// grid (CAP/128=10, EB=32), 256 threads = 8 warps (4M x 2N), warp tile 32x96
__global__ void __launch_bounds__(256) proj_kernel() {
    constexpr int AST = 36, BST = 36;
    constexpr int AW = 128 * AST;   // 4608 words/stage
    constexpr int BW = 192 * BST;   // 6912 words/stage
    extern __shared__ uint32_t dsm[];
    uint32_t* As = dsm;             // 2 stages [row][kpair] 128x32
    uint32_t* Bs = dsm + 2 * AW;    // 2 stages [n][kpair] 192x32
    int mt = blockIdx.x, eb = blockIdx.y;
    int e = eb >> 1, b = eb & 1;
    int tid = threadIdx.x;
    int lane = tid & 31, w = tid >> 5;
    int lr = lane >> 2, lc = lane & 3;
    int wm = (w & 3) * 32;
    int wn = (w >> 2) * 96;
    int m0 = mt * 128;

    // A: 128 rows x 8 chunks = 1024, 4 per thread
    const uint32_t* asrc[4];
    uint32_t asoff[4];
#pragma unroll
    for (int it = 0; it < 4; it++) {
        int idx = tid + it * 256;
        int row = idx >> 3, c = idx & 7;
        int seq = g_seq[eb * CAP + m0 + row];
        asrc[it] = g_xh + (size_t)(b * S + seq) * 512 + c * 4;
        asoff[it] = row * AST + c * 4;
    }
    // B: 192 n x 8 chunks = 1536, 6 per thread
    const uint32_t* wtbase = g_wt + (size_t)e * 192 * 512;
    const uint32_t* bsrc[6];
    uint32_t bsoff[6];
#pragma unroll
    for (int it = 0; it < 6; it++) {
        int f = tid + it * 256;
        int n = f >> 3, cb = f & 7;
        bsrc[it] = wtbase + (size_t)n * 512 + cb * 4;
        bsoff[it] = n * BST + cb * 4;
    }

    float acc[2][12][4];
#pragma unroll
    for (int i = 0; i < 2; i++)
#pragma unroll
        for (int j = 0; j < 12; j++)
#pragma unroll
            for (int r = 0; r < 4; r++) acc[i][j][r] = 0.f;

    // prologue: stage 0
#pragma unroll
    for (int it = 0; it < 4; it++)
        cp_async16((uint32_t)__cvta_generic_to_shared(As + asoff[it]), asrc[it]);
#pragma unroll
    for (int it = 0; it < 6; it++)
        cp_async16((uint32_t)__cvta_generic_to_shared(Bs + bsoff[it]), bsrc[it]);
    cp_commit();

    for (int kt = 0; kt < 16; kt++) {
        cp_wait0();
        __syncthreads();
        if (kt + 1 < 16) {
            int s = (kt + 1) & 1;
            int kp0 = (kt + 1) * 32;
#pragma unroll
            for (int it = 0; it < 4; it++)
                cp_async16((uint32_t)__cvta_generic_to_shared(As + s * AW + asoff[it]),
                           asrc[it] + kp0);
#pragma unroll
            for (int it = 0; it < 6; it++)
                cp_async16((uint32_t)__cvta_generic_to_shared(Bs + s * BW + bsoff[it]),
                           bsrc[it] + kp0);
            cp_commit();
        }
        int cs = kt & 1;
        const uint32_t* Acur = As + cs * AW;
        const uint32_t* Bcur = Bs + cs * BW;
#pragma unroll
        for (int kk = 0; kk < 4; kk++) {
            uint32_t a[2][4], bb[12][2];
#pragma unroll
            for (int mb = 0; mb < 2; mb++) {
                const uint32_t* ap = &Acur[(wm + mb * 16 + lr) * AST + kk * 8 + lc];
                a[mb][0] = ap[0];
                a[mb][1] = ap[8 * AST];
                a[mb][2] = ap[4];
                a[mb][3] = ap[8 * AST + 4];
            }
#pragma unroll
            for (int nb = 0; nb < 12; nb++) {
                const uint32_t* bp = &Bcur[(wn + nb * 8 + lr) * BST + kk * 8 + lc];
                bb[nb][0] = bp[0];
                bb[nb][1] = bp[4];
            }
#pragma unroll
            for (int mb = 0; mb < 2; mb++)
#pragma unroll
                for (int nb = 0; nb < 12; nb++)
                    mma_bf16(acc[mb][nb][0], acc[mb][nb][1], acc[mb][nb][2], acc[mb][nb][3],
                             a[mb][0], a[mb][1], a[mb][2], a[mb][3],
                             bb[nb][0], bb[nb][1]);
        }
    }

    // epilogue: cols 0-63 -> q, 64-127 -> k, 128-191 -> v
#pragma unroll
    for (int nb = 0; nb < 12; nb++) {
        int colg = wn + nb * 8 + 2 * lc;
#pragma unroll
        for (int mb = 0; mb < 2; mb++) {
            int row0 = m0 + wm + mb * 16 + lr;
            int row1 = row0 + 8;
            if (colg < 64) {
                int pair = colg >> 1;
                g_qh[(eb * CAP + row0) * 32 + pair] = packbf(acc[mb][nb][0], acc[mb][nb][1]);
                g_qh[(eb * CAP + row1) * 32 + pair] = packbf(acc[mb][nb][2], acc[mb][nb][3]);
            } else if (colg < 128) {
                int pair = (colg - 64) >> 1;
                g_kh[(eb * CAP + row0) * 32 + pair] = packbf(acc[mb][nb][0], acc[mb][nb][1]);
                g_kh[(eb * CAP + row1) * 32 + pair] = packbf(acc[mb][nb][2], acc[mb][nb][3]);
            } else {
                int col = colg - 128;
                g_vt[(size_t)(eb * HD + col) * CAP + row0]     = __float2bfloat16(acc[mb][nb][0]);
                g_vt[(size_t)(eb * HD + col + 1) * CAP + row0] = __float2bfloat16(acc[mb][nb][1]);
                g_vt[(size_t)(eb * HD + col) * CAP + row1]     = __float2bfloat16(acc[mb][nb][2]);
                g_vt[(size_t)(eb * HD + col + 1) * CAP + row1] = __float2bfloat16(acc[mb][nb][3]);
            }
        }
    }
}

// ================= stage 4b: RoPE via table =================
__global__ void rope_kernel() {
    int idx = blockIdx.x * blockDim.x + threadIdx.x;
    if (idx >= EB * CAP * 16) return;
    int j = idx & 15;
    int t = idx >> 4;
    int pos = g_seq[t];
    float2 cs0 = g_rope[pos * 32 + 2 * j];
    float2 cs1 = g_rope[pos * 32 + 2 * j + 1];
    float c0 = cs0.x, s0 = cs0.y;
    float c1 = cs1.x, s1 = cs1.y;
    uint32_t* q = g_qh + (size_t)t * 32;
    uint32_t* k = g_kh + (size_t)t * 32;
    {
        float2 a = __bfloat1622float2(*(__nv_bfloat162*)&q[j]);
        float2 b = __bfloat1622float2(*(__nv_bfloat162*)&q[j + 16]);
        q[j]      = packbf(a.x * c0 - b.x * s0, a.y * c1 - b.y * s1);
        q[j + 16] = packbf(b.x * c0 + a.x * s0, b.y * c1 + a.y * s1);
    }
    {
        float2 a = __bfloat1622float2(*(__nv_bfloat162*)&k[j]);
        float2 b = __bfloat1622float2(*(__nv_bfloat162*)&k[j + 16]);
        k[j]      = packbf(a.x * c0 - b.x * s0, a.y * c1 - b.y * s1);
        k[j + 16] = packbf(b.x * c0 + a.x * s0, b.y * c1 + a.y * s1);
    }
}

// ================= stage 5: split-KV flash attention, BF16 mma, register-resident P ====
__global__ void __launch_bounds__(256, 2) attn_kernel() {
    constexpr int ST = 36;
    extern __shared__ uint32_t dsm[];
    uint32_t* Qs   = dsm;
    uint32_t* KsB  = dsm + 128 * ST;
    uint32_t* VtsB = dsm + 256 * ST;
    int mt = 9 - blockIdx.x;
    int eb = blockIdx.y;
    int split = blockIdx.z;
    int m0 = mt * 128;
    const uint32_t* qptr = g_qh + (size_t)eb * CAP * 32;
    const uint32_t* kptr = g_kh + (size_t)eb * CAP * 32;
    const uint32_t* vtptr = (const uint32_t*)g_vt + (size_t)eb * HD * (CAP / 2);
    int tid = threadIdx.x;
    int lane = tid & 31, w = tid >> 5;
    int lr = lane >> 2, lc = lane & 3;
    int wrow = 16 * w;

    int half = mt + 1;
    int ntStart = split * half;
    int ntEnd = ntStart + half;

#pragma unroll
    for (int it = 0; it < 4; it++) {
        int idx = tid + it * 256;
        int row = idx >> 3, c = idx & 7;
        cp_async16((uint32_t)__cvta_generic_to_shared(Qs + row * ST + c * 4),
                   qptr + (size_t)(m0 + row) * 32 + c * 4);
    }
    {
        int buf = ntStart & 1;
        int n0 = ntStart * 64;
        uint32_t* Kd = KsB + buf * 64 * ST;
        uint32_t* Vd = VtsB + buf * 64 * ST;
#pragma unroll
        for (int it = 0; it < 2; it++) {
            int idx = tid + it * 256;
            int row = idx >> 3, c = idx & 7;
            cp_async16((uint32_t)__cvta_generic_to_shared(Kd + row * ST + c * 4),
                       kptr + (size_t)(n0 + row) * 32 + c * 4);
            cp_async16((uint32_t)__cvta_generic_to_shared(Vd + row * ST + c * 4),
                       vtptr + (size_t)row * (CAP / 2) + (n0 >> 1) + c * 4);
        }
        cp_commit();
    }

    float o[8][4];
#pragma unroll
    for (int t8 = 0; t8 < 8; t8++)
#pragma unroll
        for (int r = 0; r < 4; r++) o[t8][r] = 0.f;
    float mrow0 = -3.402823466e38f, mrow1 = -3.402823466e38f;
    float lsum0 = 0.f, lsum1 = 0.f;

    for (int nt = ntStart; nt < ntEnd; nt++) {
        __syncthreads();
        if (nt + 1 < ntEnd) {
            int buf = (nt + 1) & 1;
            int n0n = (nt + 1) * 64;
            uint32_t* Kd = KsB + buf * 64 * ST;
            uint32_t* Vd = VtsB + buf * 64 * ST;
#pragma unroll
            for (int it = 0; it < 2; it++) {
                int idx = tid + it * 256;
                int row = idx >> 3, c = idx & 7;
                cp_async16((uint32_t)__cvta_generic_to_shared(Kd + row * ST + c * 4),
                           kptr + (size_t)(n0n + row) * 32 + c * 4);
                cp_async16((uint32_t)__cvta_generic_to_shared(Vd + row * ST + c * 4),
                           vtptr + (size_t)row * (CAP / 2) + (n0n >> 1) + c * 4);
            }
            cp_commit();
            cp_wait1();
        } else {
            cp_wait0();
        }
        __syncthreads();

        int n0 = nt * 64;
        const uint32_t* Ks  = KsB + (nt & 1) * 64 * ST;
        const uint32_t* Vts = VtsB + (nt & 1) * 64 * ST;

        float sacc[8][4];
#pragma unroll
        for (int t8 = 0; t8 < 8; t8++)
#pragma unroll
            for (int r = 0; r < 4; r++) sacc[t8][r] = 0.f;
#pragma unroll
        for (int kk = 0; kk < 4; kk++) {
            const uint32_t* ap = &Qs[(wrow + lr) * ST + kk * 8 + lc];
            uint32_t a0 = ap[0], a1 = ap[8 * ST], a2 = ap[4], a3 = ap[8 * ST + 4];
#pragma unroll
            for (int t8 = 0; t8 < 8; t8++) {
                const uint32_t* bp = &Ks[(t8 * 8 + lr) * ST + kk * 8 + lc];
                mma_bf16(sacc[t8][0], sacc[t8][1], sacc[t8][2], sacc[t8][3],
                         a0, a1, a2, a3, bp[0], bp[4]);
            }
        }

        bool maskT = (nt >= 2 * mt);
#pragma unroll
        for (int t8 = 0; t8 < 8; t8++) {
            int cbase = n0 + t8 * 8 + 2 * lc;
#pragma unroll
            for (int r = 0; r < 4; r++) {
                float v = sacc[t8][r] * 0.125f;
                if (maskT) {
                    int row = m0 + wrow + lr + ((r >= 2) ? 8 : 0);
                    int col = cbase + (r & 1);
                    if (col > row) v = -3.402823466e38f;
                }
                sacc[t8][r] = v;
            }
        }

        float mx0 = -3.402823466e38f, mx1 = -3.402823466e38f;
#pragma unroll
        for (int t8 = 0; t8 < 8; t8++) {
            mx0 = fmaxf(mx0, fmaxf(sacc[t8][0], sacc[t8][1]));
            mx1 = fmaxf(mx1, fmaxf(sacc[t8][2], sacc[t8][3]));
        }
        mx0 = fmaxf(mx0, __shfl_xor_sync(0xffffffffu, mx0, 1));
        mx0 = fmaxf(mx0, __shfl_xor_sync(0xffffffffu, mx0, 2));
        mx1 = fmaxf(mx1, __shfl_xor_sync(0xffffffffu, mx1, 1));
        mx1 = fmaxf(mx1, __shfl_xor_sync(0xffffffffu, mx1, 2));
        float nm0 = fmaxf(mrow0, mx0), nm1 = fmaxf(mrow1, mx1);
        float corr0 = __expf(mrow0 - nm0), corr1 = __expf(mrow1 - nm1);
        float rs0 = 0.f, rs1 = 0.f;
        uint32_t pp0[8], pp1[8];
#pragma unroll
        for (int t8 = 0; t8 < 8; t8++) {
            float p0 = __expf(sacc[t8][0] - nm0);
            float p1 = __expf(sacc[t8][1] - nm0);
            float p2 = __expf(sacc[t8][2] - nm1);
            float p3 = __expf(sacc[t8][3] - nm1);
            rs0 += p0 + p1; rs1 += p2 + p3;
            pp0[t8] = packbf(p0, p1);
            pp1[t8] = packbf(p2, p3);
        }
        rs0 += __shfl_xor_sync(0xffffffffu, rs0, 1);
        rs0 += __shfl_xor_sync(0xffffffffu, rs0, 2);
        rs1 += __shfl_xor_sync(0xffffffffu, rs1, 1);
        rs1 += __shfl_xor_sync(0xffffffffu, rs1, 2);
        lsum0 = lsum0 * corr0 + rs0;
        lsum1 = lsum1 * corr1 + rs1;
        mrow0 = nm0; mrow1 = nm1;
#pragma unroll
        for (int t8 = 0; t8 < 8; t8++) {
            o[t8][0] *= corr0; o[t8][1] *= corr0;
            o[t8][2] *= corr1; o[t8][3] *= corr1;
        }

#pragma unroll
        for (int kk = 0; kk < 4; kk++) {
            uint32_t a0 = pp0[2 * kk];
            uint32_t a1 = pp1[2 * kk];
            uint32_t a2 = pp0[2 * kk + 1];
            uint32_t a3 = pp1[2 * kk + 1];
#pragma unroll
            for (int t8 = 0; t8 < 8; t8++) {
                const uint32_t* bp = &Vts[(t8 * 8 + lr) * ST + kk * 8 + lc];
                mma_bf16(o[t8][0], o[t8][1], o[t8][2], o[t8][3],
                         a0, a1, a2, a3, bp[0], bp[4]);
            }
        }
    }

    int row0 = m0 + wrow + lr, row1 = row0 + 8;
    float* op = g_opart + (size_t)split * EB * CAP * HD;
#pragma unroll
    for (int t8 = 0; t8 < 8; t8++) {
        int col = t8 * 8 + 2 * lc;
        *(float2*)(op + ((size_t)eb * CAP + row0) * HD + col) = make_float2(o[t8][0], o[t8][1]);
        *(float2*)(op + ((size_t)eb * CAP + row1) * HD + col) = make_float2(o[t8][2], o[t8][3]);
    }
    if (lc == 0) {
        int base = split * EB * CAP + eb * CAP;
        g_pm[base + row0] = mrow0;
        g_pl[base + row0] = lsum0;
        g_pm[base + row1] = mrow1;
        g_pl[base + row1] = lsum1;
    }
}

// ================= stage 5b: combine splits -> packed bf16 ctx =================
__global__ void combine_kernel() {
    int idx = blockIdx.x * blockDim.x + threadIdx.x;
    if (idx >= EB * CAP * 16) return;
    int t = idx >> 4;
    int c4 = (idx & 15) << 2;
    float m0 = g_pm[t], m1 = g_pm[EB * CAP + t];
    float l0 = g_pl[t], l1 = g_pl[EB * CAP + t];
    float M = fmaxf(m0, m1);
    float s0 = __expf(m0 - M), s1 = __expf(m1 - M);
    float inv = 1.f / (l0 * s0 + l1 * s1);
    const float4 a = *(const float4*)(g_opart + (size_t)t * HD + c4);
    const float4 b = *(const float4*)(g_opart + (size_t)EB * CAP * HD + (size_t)t * HD + c4);
    uint2 o;
    o.x = packbf((a.x * s0 + b.x * s1) * inv, (a.y * s0 + b.y * s1) * inv);
    o.y = packbf((a.z * s0 + b.z * s1) * inv, (a.w * s0 + b.w * s1) * inv);
    *(uint2*)(g_ctxh + (size_t)t * 32 + (c4 >> 1)) = o;
}

// ================= stage 6a: out = (ctx @ Wff + bff) * w -> bf16 g_out (BF16 mma) =====
__global__ void __launch_bounds__(256) outproj_kernel(const float* __restrict__ bff) {
    constexpr int AST = 36, BST = 36;
    extern __shared__ uint32_t dsm[];
    uint32_t* As = dsm;
    uint32_t* Bs = As + 128 * AST;
    int mt = blockIdx.x, nt = blockIdx.y, eb = blockIdx.z;
    int e = eb >> 1;
    int tid = threadIdx.x;
    int lane = tid & 31, w = tid >> 5;
    int lr = lane >> 2, lc = lane & 3;
    int wm = (w & 3) * 32, wn = (w >> 2) * 64;
    int m0 = mt * 128, n0 = nt * 128;

#pragma unroll
    for (int it = 0; it < 4; it++) {
        int idx = tid + it * 256;
        int row = idx >> 3, c = idx & 7;
        cp_async16((uint32_t)__cvta_generic_to_shared(As + row * AST + c * 4),
                   g_ctxh + (size_t)(eb * CAP + m0 + row) * 32 + c * 4);
    }
#pragma unroll
    for (int it = 0; it < 4; it++) {
        int idx = tid + it * 256;
        int n = idx >> 3, c = idx & 7;
        cp_async16((uint32_t)__cvta_generic_to_shared(Bs + n * BST + c * 4),
                   g_wfft + (size_t)(e * 1024 + n0 + n) * 32 + c * 4);
    }
    cp_commit();
    cp_wait0();
    __syncthreads();

    float acc[2][8][4];
#pragma unroll
    for (int mi = 0; mi < 2; mi++)
#pragma unroll
        for (int t8 = 0; t8 < 8; t8++)
#pragma unroll
            for (int r = 0; r < 4; r++) acc[mi][t8][r] = 0.f;

#pragma unroll
    for (int kk = 0; kk < 4; kk++) {
        uint32_t a[2][4];
#pragma unroll
        for (int mi = 0; mi < 2; mi++) {
            const uint32_t* ap = &As[(wm + mi * 16 + lr) * AST + kk * 8 + lc];
            a[mi][0] = ap[0]; a[mi][1] = ap[8 * AST];
            a[mi][2] = ap[4]; a[mi][3] = ap[8 * AST + 4];
        }
#pragma unroll
        for (int t8 = 0; t8 < 8; t8++) {
            const uint32_t* bp = &Bs[(wn + t8 * 8 + lr) * BST + kk * 8 + lc];
#pragma unroll
            for (int mi = 0; mi < 2; mi++)
                mma_bf16(acc[mi][t8][0], acc[mi][t8][1], acc[mi][t8][2], acc[mi][t8][3],
                         a[mi][0], a[mi][1], a[mi][2], a[mi][3], bp[0], bp[4]);
        }
    }

#pragma unroll
    for (int mi = 0; mi < 2; mi++) {
        int row0 = m0 + wm + mi * 16 + lr;
        int row1 = row0 + 8;
        float wv0 = g_w[eb * CAP + row0];
        float wv1 = g_w[eb * CAP + row1];
#pragma unroll
        for (int t8 = 0; t8 < 8; t8++) {
            int col = n0 + wn + t8 * 8 + 2 * lc;
            float2 bf = *(const float2*)(bff + col);
            if (wv0 != 0.f) {
                __nv_bfloat162 v;
                v.x = __float2bfloat16((acc[mi][t8][0] + bf.x) * wv0);
                v.y = __float2bfloat16((acc[mi][t8][1] + bf.y) * wv0);
                *(__nv_bfloat162*)(g_out + ((size_t)eb * CAP + row0) * D + col) = v;
            }
            if (wv1 != 0.f) {
                __nv_bfloat162 v;
                v.x = __float2bfloat16((acc[mi][t8][2] + bf.x) * wv1);
                v.y = __float2bfloat16((acc[mi][t8][3] + bf.y) * wv1);
                *(__nv_bfloat162*)(g_out + ((size_t)eb * CAP + row1) * D + col) = v;
            }
        }
    }
}

// ================= stage 6b: gather-combine + residual + LayerNorm =================
__global__ void ln_kernel(const float* __restrict__ x,
                          const float* __restrict__ gamma,
                          const float* __restrict__ beta,
                          float* __restrict__ out) {
    int token = blockIdx.x;
    int b = token >> 11;
    int tid = threadIdx.x;
    __shared__ int sh_base[E];
    __shared__ float red[8];
    if (tid < E) {
        int p = g_inv[tid * NTOK + token];
        int base = -1;
        if (p >= 0) {
            int idx = (tid * B + b) * CAP + p;
            if (g_w[idx] != 0.f) base = idx;
        }
        sh_base[tid] = base;
    }
    __syncthreads();
    float4 c = make_float4(0.f, 0.f, 0.f, 0.f);
#pragma unroll
    for (int e = 0; e < E; e++) {
        int base = sh_base[e];
        if (base >= 0) {
            uint2 u = *(const uint2*)(g_out + (size_t)base * D + tid * 4);
            __nv_bfloat162 p0 = *reinterpret_cast<__nv_bfloat162*>(&u.x);
            __nv_bfloat162 p1 = *reinterpret_cast<__nv_bfloat162*>(&u.y);
            c.x += __bfloat162float(p0.x); c.y += __bfloat162float(p0.y);
            c.z += __bfloat162float(p1.x); c.w += __bfloat162float(p1.y);
        }
    }
    float4 x4 = *(const float4*)(x + (size_t)token * D + tid * 4);
    float h[4] = {x4.x + c.x, x4.y + c.y, x4.z + c.z, x4.w + c.w};
    float s = h[0] + h[1] + h[2] + h[3];
#pragma unroll
    for (int off = 16; off > 0; off >>= 1) s += __shfl_xor_sync(0xffffffffu, s, off);
    int warp = tid >> 5, lane = tid & 31;
    if (lane == 0) red[warp] = s;
    __syncthreads();
    float total = 0.f;
#pragma unroll
    for (int w = 0; w < 8; w++) total += red[w];
    __syncthreads();
    float mu = total * (1.0f / D);
    float ss = 0.f;
#pragma unroll
    for (int t = 0; t < 4; t++) {
        float dlt = h[t] - mu;
        ss += dlt * dlt;
    }
#pragma unroll
    for (int off = 16; off > 0; off >>= 1) ss += __shfl_xor_sync(0xffffffffu, ss, off);
    if (lane == 0) red[warp] = ss;
    __syncthreads();
    float vtot = 0.f;
#pragma unroll
    for (int w = 0; w < 8; w++) vtot += red[w];
    float var = vtot * (1.0f / D);
    float inv = rsqrtf(var + 1e-5f);
    float4 g4 = *(const float4*)(gamma + tid * 4);
    float4 be4 = *(const float4*)(beta + tid * 4);
    float4 o4;
    o4.x = (h[0] - mu) * inv * g4.x + be4.x;
    o4.y = (h[1] - mu) * inv * g4.y + be4.y;
    o4.z = (h[2] - mu) * inv * g4.z + be4.z;
    o4.w = (h[3] - mu) * inv * g4.w + be4.w;
    *(float4*)(out + (size_t)token * D + tid * 4) = o4;
}

// ================= launch =================
extern "C" void kernel_launch(void* const* d_in, const int* in_sizes, int n_in,
                              void* d_out, int out_size) {
    const float* x     = (const float*)d_in[0];
    const float* wg    = (const float*)d_in[1];
    const float* bg    = (const float*)d_in[2];
    const float* Wq    = (const float*)d_in[3];
    const float* Wkv   = (const float*)d_in[4];
    const float* Wff   = (const float*)d_in[5];
    const float* bff   = (const float*)d_in[6];
    const float* gamma = (const float*)d_in[7];
    const float* beta  = (const float*)d_in[8];
    float* out = (float*)d_out;

    (void)in_sizes; (void)n_in; (void)out_size;

    wgt_kernel<<<E * D / 256, 256>>>(wg);
    fat_kernel<<<3840, 256>>>(x, bg, Wq, Wkv, Wff);

    mask_kernel<<<dim3(EB, 8), 256>>>();
    select_kernel<<<dim3(EB, 8), 256>>>();

    int proj_smem = 2 * (128 * 36 + 192 * 36) * (int)sizeof(uint32_t);  // 92,160 B
    cudaFuncSetAttribute(proj_kernel, cudaFuncAttributeMaxDynamicSharedMemorySize, proj_smem);
    proj_kernel<<<dim3(CAP / 128, EB), 256, proj_smem>>>();

    rope_kernel<<<(EB * CAP * 16 + 255) / 256, 256>>>();

    int attn_smem = 384 * 36 * (int)sizeof(uint32_t);   // 55,296 B
    cudaFuncSetAttribute(attn_kernel, cudaFuncAttributeMaxDynamicSharedMemorySize, attn_smem);
    attn_kernel<<<dim3(CAP / 128, EB, 2), 256, attn_smem>>>();

    combine_kernel<<<(EB * CAP * 16 + 255) / 256, 256>>>();

    int op_smem = 2 * 128 * 36 * (int)sizeof(uint32_t);  // 36,864 B
    cudaFuncSetAttribute(outproj_kernel, cudaFuncAttributeMaxDynamicSharedMemorySize, op_smem);
    outproj_kernel<<<dim3(CAP / 128, D / 128, EB), 256, op_smem>>>(bff);

    ln_kernel<<<NTOK, 256>>>(x, gamma, beta, out);
}

// round 17
// speedup vs baseline: 1.0142x; 1.0142x over previous
#include <cuda_runtime.h>
#include <cuda_bf16.h>
#include <math.h>
#include <stdint.h>

// ---------------- problem constants ----------------
namespace {
constexpr int B = 2, S = 2048, D = 1024, E = 16, HD = 64, CAP = 1280, TOPK = 8;
constexpr float EPS = 1e-6f;
constexpr int EB = E * B;    // 32
constexpr int NTOK = B * S;  // 4096
constexpr int MAXPOS = 2048;
}

// ---------------- scratch (device globals; no allocation allowed) ----------------
__device__ float g_route[NTOK * E];
__device__ float g_routeT[EB * S];
__device__ float g_wgt[E * D];
__device__ unsigned char g_mask[EB * S];
__device__ int   g_cnt[EB * 8];
__device__ float2 g_rope[MAXPOS * 32];
__device__ int   g_seq[EB * CAP];
__device__ float g_w[EB * CAP];
__device__ int   g_inv[E * NTOK];
__device__ uint32_t g_xh[NTOK * 512];
__device__ uint32_t g_wt[(size_t)E * 192 * 512];
__device__ uint32_t g_wfft[(size_t)E * 1024 * 32];
__device__ uint32_t g_qh[EB * CAP * 32];
__device__ uint32_t g_kh[EB * CAP * 32];
__device__ __nv_bfloat16 g_vt[(size_t)EB * HD * CAP];
__device__ uint32_t g_ctxh[EB * CAP * 32];
__device__ float g_opart[2 * EB * CAP * HD];
__device__ float g_pm[2 * EB * CAP];
__device__ float g_pl[2 * EB * CAP];
__device__ __nv_bfloat16 g_out[(size_t)EB * CAP * D];

// ---------------- helpers ----------------
__device__ __forceinline__ void mma_bf16(float& c0, float& c1, float& c2, float& c3,
                                         uint32_t a0, uint32_t a1, uint32_t a2, uint32_t a3,
                                         uint32_t b0, uint32_t b1) {
    asm volatile(
        "mma.sync.aligned.m16n8k16.row.col.f32.bf16.bf16.f32 "
        "{%0,%1,%2,%3}, {%4,%5,%6,%7}, {%8,%9}, {%0,%1,%2,%3};\n"
        : "+f"(c0), "+f"(c1), "+f"(c2), "+f"(c3)
        : "r"(a0), "r"(a1), "r"(a2), "r"(a3), "r"(b0), "r"(b1));
}
__device__ __forceinline__ uint32_t packbf(float a, float b) {
    __nv_bfloat162 t = __floats2bfloat162_rn(a, b);
    return *reinterpret_cast<uint32_t*>(&t);
}
__device__ __forceinline__ void cp_async16(uint32_t saddr, const void* g) {
    asm volatile("cp.async.ca.shared.global [%0], [%1], 16;" :: "r"(saddr), "l"(g));
}
__device__ __forceinline__ void cp_commit() { asm volatile("cp.async.commit_group;"); }
__device__ __forceinline__ void cp_wait0()  { asm volatile("cp.async.wait_group 0;"); }
__device__ __forceinline__ void cp_wait1()  { asm volatile("cp.async.wait_group 1;"); }

// ================= prep: transpose gate weights =================
__global__ void wgt_kernel(const float* __restrict__ wg) {
    int idx = blockIdx.x * 256 + threadIdx.x;
    int d = idx >> 4, e = idx & 15;
    g_wgt[e * D + d] = wg[idx];
}

// ================= fat front-end: gate | xpack | wt | wff | rope-table =================
__global__ void __launch_bounds__(256) fat_kernel(const float* __restrict__ x,
                                                  const float* __restrict__ bg,
                                                  const float* __restrict__ Wq,
                                                  const float* __restrict__ Wkv,
                                                  const float* __restrict__ Wff) {
    __shared__ float sm[64][65];
    int bx = blockIdx.x;
    int tid = threadIdx.x;

    if (bx < 512) {
        int warp = tid >> 5;
        int lane = tid & 31;
        int token = bx * 8 + warp;
        const float4* xr = (const float4*)(x + (size_t)token * D);
        float acc[E];
#pragma unroll
        for (int e = 0; e < E; e++) acc[e] = 0.f;
#pragma unroll
        for (int it = 0; it < 8; it++) {
            float4 xv = xr[lane + it * 32];
#pragma unroll
            for (int e = 0; e < E; e++) {
                float4 wv = *(const float4*)(g_wgt + e * D + (lane + it * 32) * 4);
                acc[e] += xv.x * wv.x + xv.y * wv.y + xv.z * wv.z + xv.w * wv.w;
            }
        }
#pragma unroll
        for (int off = 16; off; off >>= 1) {
#pragma unroll
            for (int e = 0; e < E; e++)
                acc[e] += __shfl_xor_sync(0xffffffffu, acc[e], off);
        }
        if (lane == 0) {
            float g[E];
            float mx = -3.402823466e38f;
#pragma unroll
            for (int e = 0; e < E; e++) {
                g[e] = acc[e] + bg[e];
                mx = fmaxf(mx, g[e]);
            }
            float den = 0.f;
#pragma unroll
            for (int e = 0; e < E; e++) { g[e] = expf(g[e] - mx); den += g[e]; }
            float inv = 1.f / den;
#pragma unroll
            for (int e = 0; e < E; e++) g[e] *= inv;
#pragma unroll
            for (int e = 0; e < E; e++) {
                int r = 0;
#pragma unroll
                for (int j = 0; j < E; j++)
                    r += (g[j] > g[e]) || (g[j] == g[e] && j < e);
                g_route[(size_t)token * E + e] = (r < TOPK) ? g[e] : 0.f;
            }
        }
    } else if (bx < 2560) {
        int idx = (bx - 512) * 256 + tid;
        const float4* src = (const float4*)x + (size_t)idx * 2;
        float4 v0 = src[0];
        float4 v1 = src[1];
        uint4 o;
        o.x = packbf(v0.x, v0.y);
        o.y = packbf(v0.z, v0.w);
        o.z = packbf(v1.x, v1.y);
        o.w = packbf(v1.z, v1.w);
        *((uint4*)g_xh + idx) = o;
    } else if (bx < 3328) {
        int i = bx - 2560;
        int e = i / 48;
        int rem = i % 48;
        int k0 = (rem / 3) * 64;
        int nz = rem % 3;
        int n0 = nz * 64;
        const float* src;
        int stride;
        if (nz == 0) { src = Wq + (size_t)e * D * HD; stride = HD; }
        else         { src = Wkv + (size_t)e * D * 128 + (n0 - 64); stride = 128; }
#pragma unroll
        for (int it = 0; it < 16; it++) {
            int idx = tid + it * 256;
            int kk = idx >> 6, nn = idx & 63;
            sm[kk][nn] = src[(size_t)(k0 + kk) * stride + nn];
        }
        __syncthreads();
#pragma unroll
        for (int it = 0; it < 8; it++) {
            int idx = tid + it * 256;
            int n = idx >> 5, kp = idx & 31;
            g_wt[((size_t)(e * 192 + n0 + n)) * 512 + (k0 >> 1) + kp] =
                packbf(sm[2 * kp][n], sm[2 * kp + 1][n]);
        }
    } else if (bx < 3584) {
        int i = bx - 3328;
        int e = i >> 4;
        int n0 = (i & 15) * 64;
#pragma unroll
        for (int it = 0; it < 16; it++) {
            int idx = tid + it * 256;
            int kk = idx >> 6, nn = idx & 63;
            sm[kk][nn] = Wff[(size_t)e * HD * D + (size_t)kk * D + n0 + nn];
        }
        __syncthreads();
#pragma unroll
        for (int it = 0; it < 8; it++) {
            int idx = tid + it * 256;
            int n = idx >> 5, kp = idx & 31;
            g_wfft[((size_t)(e * 1024 + n0 + n)) * 32 + kp] =
                packbf(sm[2 * kp][n], sm[2 * kp + 1][n]);
        }
    } else {
        int idx = (bx - 3584) * 256 + tid;
        int pos = idx >> 5, h = idx & 31;
        float invf = exp2f(-(float)h * 0.4152410118609203f);
        float sv, cv;
        sincosf((float)pos * invf, &sv, &cv);
        g_rope[idx] = make_float2(cv, sv);
    }
}

// ================= stage 3a: normalize + rank mask + counts + g_inv init =================
__global__ void mask_kernel() {
    int eb = blockIdx.x;
    int e = eb >> 1, b = eb & 1;
    __shared__ float sv[S];
    int tid = threadIdx.x;
    for (int s = tid; s < S; s += 256) {
        float m0 = g_route[(size_t)s * E + e];
        float m1 = g_route[(size_t)(S + s) * E + e];
        float den = m0 + m1 + EPS;
        sv[s] = (b ? m1 : m0) / den * 2.0f;
    }
    __syncthreads();
    if (blockIdx.y == 0) {
        for (int s = tid; s < S; s += 256)
            g_routeT[eb * S + s] = sv[s];
    }
    int i = blockIdx.y * 256 + tid;
    float vi = sv[i];
    int c = 0;
#pragma unroll 4
    for (int j4 = 0; j4 < S / 4; j4++) {
        float4 v = *(const float4*)(sv + j4 * 4);
        int j = j4 * 4;
        c += (v.x > vi) || (v.x == vi && (j + 0) < i);
        c += (v.y > vi) || (v.y == vi && (j + 1) < i);
        c += (v.z > vi) || (v.z == vi && (j + 2) < i);
        c += (v.w > vi) || (v.w == vi && (j + 3) < i);
    }
    int sel = (c < CAP) ? 1 : 0;
    g_mask[eb * S + i] = (unsigned char)sel;
    g_inv[e * NTOK + b * S + i] = -1;
    int total = __syncthreads_count(sel);
    if (tid == 0) g_cnt[eb * 8 + blockIdx.y] = total;
}

// ================= stage 3b: compaction =================
__global__ void select_kernel() {
    int eb = blockIdx.x, y = blockIdx.y;
    int e = eb >> 1, b = eb & 1;
    __shared__ int wsum[8];
    int t = threadIdx.x;
    int base = 0;
#pragma unroll
    for (int yy = 0; yy < 8; yy++)
        if (yy < y) base += g_cnt[eb * 8 + yy];
    int i = y * 256 + t;
    int sel = g_mask[eb * S + i];
    int lane = t & 31, warp = t >> 5;
    int scan = sel;
#pragma unroll
    for (int off = 1; off < 32; off <<= 1) {
        int v = __shfl_up_sync(0xffffffffu, scan, off);
        if (lane >= off) scan += v;
    }
    if (lane == 31) wsum[warp] = scan;
    __syncthreads();
#pragma unroll
    for (int wi = 0; wi < 8; wi++)
        if (wi < warp) base += wsum[wi];
    if (sel) {
        int pos = base + scan - sel;
        g_seq[eb * CAP + pos] = i;
        g_w[eb * CAP + pos] = g_routeT[eb * S + i];
        g_inv[e * NTOK + b * S + i] = pos;
    }
}

// ================= stage 4a: fused Q/K/V projection, BF16 mma (M=64, proven) =========
__global__ void __launch_bounds__(256) proj_kernel() {
    constexpr int AST = 36, BST = 36;
    constexpr int AW = 64 * AST;
    constexpr int BW = 192 * BST;
    extern __shared__ uint32_t dsm[];
    uint32_t* As = dsm;
    uint32_t* Bs = dsm + 2 * AW;
    int mt = blockIdx.x, eb = blockIdx.y;
    int e = eb >> 1, b = eb & 1;
    int tid = threadIdx.x;
    int lane = tid & 31, w = tid >> 5;
    int lr = lane >> 2, lc = lane & 3;
    int wm = (w & 1) * 32;
    int wn = (w >> 1) * 48;
    int m0 = mt * 64;

    int r0 = tid >> 3;
    int c = tid & 7;
    int seq0 = g_seq[eb * CAP + m0 + r0];
    int seq1 = g_seq[eb * CAP + m0 + r0 + 32];
    const uint32_t* arow0 = g_xh + (size_t)(b * S + seq0) * 512 + c * 4;
    const uint32_t* arow1 = g_xh + (size_t)(b * S + seq1) * 512 + c * 4;
    uint32_t as0 = r0 * AST + c * 4;
    uint32_t as1 = (r0 + 32) * AST + c * 4;

    const uint32_t* wtbase = g_wt + (size_t)e * 192 * 512;
    const uint32_t* bsrc[6];
    uint32_t bsoff[6];
#pragma unroll
    for (int it = 0; it < 6; it++) {
        int f = tid + it * 256;
        int n = f >> 3, cb = f & 7;
        bsrc[it] = wtbase + (size_t)n * 512 + cb * 4;
        bsoff[it] = n * BST + cb * 4;
    }

    float acc[2][6][4];
#pragma unroll
    for (int i = 0; i < 2; i++)
#pragma unroll
        for (int j = 0; j < 6; j++)
#pragma unroll
            for (int r = 0; r < 4; r++) acc[i][j][r] = 0.f;

    cp_async16((uint32_t)__cvta_generic_to_shared(As + as0), arow0);
    cp_async16((uint32_t)__cvta_generic_to_shared(As + as1), arow1);
#pragma unroll
    for (int it = 0; it < 6; it++)
        cp_async16((uint32_t)__cvta_generic_to_shared(Bs + bsoff[it]), bsrc[it]);
    cp_commit();

    for (int kt = 0; kt < 16; kt++) {
        cp_wait0();
        __syncthreads();
        if (kt + 1 < 16) {
            int s = (kt + 1) & 1;
            int kp0 = (kt + 1) * 32;
            cp_async16((uint32_t)__cvta_generic_to_shared(As + s * AW + as0), arow0 + kp0);
            cp_async16((uint32_t)__cvta_generic_to_shared(As + s * AW + as1), arow1 + kp0);
#pragma unroll
            for (int it = 0; it < 6; it++)
                cp_async16((uint32_t)__cvta_generic_to_shared(Bs + s * BW + bsoff[it]),
                           bsrc[it] + kp0);
            cp_commit();
        }
        int cs = kt & 1;
        const uint32_t* Acur = As + cs * AW;
        const uint32_t* Bcur = Bs + cs * BW;
#pragma unroll
        for (int kk = 0; kk < 4; kk++) {
            uint32_t a[2][4], bb[6][2];
#pragma unroll
            for (int mb = 0; mb < 2; mb++) {
                const uint32_t* ap = &Acur[(wm + mb * 16 + lr) * AST + kk * 8 + lc];
                a[mb][0] = ap[0];
                a[mb][1] = ap[8 * AST];
                a[mb][2] = ap[4];
                a[mb][3] = ap[8 * AST + 4];
            }
#pragma unroll
            for (int nb = 0; nb < 6; nb++) {
                const uint32_t* bp = &Bcur[(wn + nb * 8 + lr) * BST + kk * 8 + lc];
                bb[nb][0] = bp[0];
                bb[nb][1] = bp[4];
            }
#pragma unroll
            for (int mb = 0; mb < 2; mb++)
#pragma unroll
                for (int nb = 0; nb < 6; nb++)
                    mma_bf16(acc[mb][nb][0], acc[mb][nb][1], acc[mb][nb][2], acc[mb][nb][3],
                             a[mb][0], a[mb][1], a[mb][2], a[mb][3],
                             bb[nb][0], bb[nb][1]);
        }
    }

#pragma unroll
    for (int nb = 0; nb < 6; nb++) {
        int colg = wn + nb * 8 + 2 * lc;
#pragma unroll
        for (int mb = 0; mb < 2; mb++) {
            int row0 = m0 + wm + mb * 16 + lr;
            int row1 = row0 + 8;
            if (colg < 64) {
                int pair = colg >> 1;
                g_qh[(eb * CAP + row0) * 32 + pair] = packbf(acc[mb][nb][0], acc[mb][nb][1]);
                g_qh[(eb * CAP + row1) * 32 + pair] = packbf(acc[mb][nb][2], acc[mb][nb][3]);
            } else if (colg < 128) {
                int pair = (colg - 64) >> 1;
                g_kh[(eb * CAP + row0) * 32 + pair] = packbf(acc[mb][nb][0], acc[mb][nb][1]);
                g_kh[(eb * CAP + row1) * 32 + pair] = packbf(acc[mb][nb][2], acc[mb][nb][3]);
            } else {
                int col = colg - 128;
                g_vt[(size_t)(eb * HD + col) * CAP + row0]     = __float2bfloat16(acc[mb][nb][0]);
                g_vt[(size_t)(eb * HD + col + 1) * CAP + row0] = __float2bfloat16(acc[mb][nb][1]);
                g_vt[(size_t)(eb * HD + col) * CAP + row1]     = __float2bfloat16(acc[mb][nb][2]);
                g_vt[(size_t)(eb * HD + col + 1) * CAP + row1] = __float2bfloat16(acc[mb][nb][3]);
            }
        }
    }
}

// ================= stage 4b: RoPE via table; q pre-scaled by 0.125 (exact) =============
__global__ void rope_kernel() {
    int idx = blockIdx.x * blockDim.x + threadIdx.x;
    if (idx >= EB * CAP * 16) return;
    int j = idx & 15;
    int t = idx >> 4;
    int pos = g_seq[t];
    float2 cs0 = g_rope[pos * 32 + 2 * j];
    float2 cs1 = g_rope[pos * 32 + 2 * j + 1];
    float c0 = cs0.x, s0 = cs0.y;
    float c1 = cs1.x, s1 = cs1.y;
    uint32_t* q = g_qh + (size_t)t * 32;
    uint32_t* k = g_kh + (size_t)t * 32;
    {
        float2 a = __bfloat1622float2(*(__nv_bfloat162*)&q[j]);
        float2 b = __bfloat1622float2(*(__nv_bfloat162*)&q[j + 16]);
        q[j]      = packbf(0.125f * (a.x * c0 - b.x * s0), 0.125f * (a.y * c1 - b.y * s1));
        q[j + 16] = packbf(0.125f * (b.x * c0 + a.x * s0), 0.125f * (b.y * c1 + a.y * s1));
    }
    {
        float2 a = __bfloat1622float2(*(__nv_bfloat162*)&k[j]);
        float2 b = __bfloat1622float2(*(__nv_bfloat162*)&k[j + 16]);
        k[j]      = packbf(a.x * c0 - b.x * s0, a.y * c1 - b.y * s1);
        k[j + 16] = packbf(b.x * c0 + a.x * s0, b.y * c1 + a.y * s1);
    }
}

// ================= stage 5: split-KV flash attention, BF16 mma, register-resident P ====
__global__ void __launch_bounds__(256, 2) attn_kernel() {
    constexpr int ST = 36;
    extern __shared__ uint32_t dsm[];
    uint32_t* Qs   = dsm;
    uint32_t* KsB  = dsm + 128 * ST;
    uint32_t* VtsB = dsm + 256 * ST;
    int mt = 9 - blockIdx.x;
    int eb = blockIdx.y;
    int split = blockIdx.z;
    int m0 = mt * 128;
    const uint32_t* qptr = g_qh + (size_t)eb * CAP * 32;
    const uint32_t* kptr = g_kh + (size_t)eb * CAP * 32;
    const uint32_t* vtptr = (const uint32_t*)g_vt + (size_t)eb * HD * (CAP / 2);
    int tid = threadIdx.x;
    int lane = tid & 31, w = tid >> 5;
    int lr = lane >> 2, lc = lane & 3;
    int wrow = 16 * w;

    int half = mt + 1;
    int ntStart = split * half;
    int ntEnd = ntStart + half;

#pragma unroll
    for (int it = 0; it < 4; it++) {
        int idx = tid + it * 256;
        int row = idx >> 3, c = idx & 7;
        cp_async16((uint32_t)__cvta_generic_to_shared(Qs + row * ST + c * 4),
                   qptr + (size_t)(m0 + row) * 32 + c * 4);
    }
    {
        int buf = ntStart & 1;
        int n0 = ntStart * 64;
        uint32_t* Kd = KsB + buf * 64 * ST;
        uint32_t* Vd = VtsB + buf * 64 * ST;
#pragma unroll
        for (int it = 0; it < 2; it++) {
            int idx = tid + it * 256;
            int row = idx >> 3, c = idx & 7;
            cp_async16((uint32_t)__cvta_generic_to_shared(Kd + row * ST + c * 4),
                       kptr + (size_t)(n0 + row) * 32 + c * 4);
            cp_async16((uint32_t)__cvta_generic_to_shared(Vd + row * ST + c * 4),
                       vtptr + (size_t)row * (CAP / 2) + (n0 >> 1) + c * 4);
        }
        cp_commit();
    }

    float o[8][4];
#pragma unroll
    for (int t8 = 0; t8 < 8; t8++)
#pragma unroll
        for (int r = 0; r < 4; r++) o[t8][r] = 0.f;
    float mrow0 = -3.402823466e38f, mrow1 = -3.402823466e38f;
    float lsum0 = 0.f, lsum1 = 0.f;

    for (int nt = ntStart; nt < ntEnd; nt++) {
        __syncthreads();
        if (nt + 1 < ntEnd) {
            int buf = (nt + 1) & 1;
            int n0n = (nt + 1) * 64;
            uint32_t* Kd = KsB + buf * 64 * ST;
            uint32_t* Vd = VtsB + buf * 64 * ST;
#pragma unroll
            for (int it = 0; it < 2; it++) {
                int idx = tid + it * 256;
                int row = idx >> 3, c = idx & 7;
                cp_async16((uint32_t)__cvta_generic_to_shared(Kd + row * ST + c * 4),
                           kptr + (size_t)(n0n + row) * 32 + c * 4);
                cp_async16((uint32_t)__cvta_generic_to_shared(Vd + row * ST + c * 4),
                           vtptr + (size_t)row * (CAP / 2) + (n0n >> 1) + c * 4);
            }
            cp_commit();
            cp_wait1();
        } else {
            cp_wait0();
        }
        __syncthreads();

        int n0 = nt * 64;
        const uint32_t* Ks  = KsB + (nt & 1) * 64 * ST;
        const uint32_t* Vts = VtsB + (nt & 1) * 64 * ST;

        float sacc[8][4];
#pragma unroll
        for (int t8 = 0; t8 < 8; t8++)
#pragma unroll
            for (int r = 0; r < 4; r++) sacc[t8][r] = 0.f;
#pragma unroll
        for (int kk = 0; kk < 4; kk++) {
            const uint32_t* ap = &Qs[(wrow + lr) * ST + kk * 8 + lc];
            uint32_t a0 = ap[0], a1 = ap[8 * ST], a2 = ap[4], a3 = ap[8 * ST + 4];
#pragma unroll
            for (int t8 = 0; t8 < 8; t8++) {
                const uint32_t* bp = &Ks[(t8 * 8 + lr) * ST + kk * 8 + lc];
                mma_bf16(sacc[t8][0], sacc[t8][1], sacc[t8][2], sacc[t8][3],
                         a0, a1, a2, a3, bp[0], bp[4]);
            }
        }

        // scores already scaled (q pre-scaled by 0.125); only diagonal tiles need masking
        if (nt >= 2 * mt) {
#pragma unroll
            for (int t8 = 0; t8 < 8; t8++) {
                int cbase = n0 + t8 * 8 + 2 * lc;
#pragma unroll
                for (int r = 0; r < 4; r++) {
                    int row = m0 + wrow + lr + ((r >= 2) ? 8 : 0);
                    int col = cbase + (r & 1);
                    if (col > row) sacc[t8][r] = -3.402823466e38f;
                }
            }
        }

        float mx0 = -3.402823466e38f, mx1 = -3.402823466e38f;
#pragma unroll
        for (int t8 = 0; t8 < 8; t8++) {
            mx0 = fmaxf(mx0, fmaxf(sacc[t8][0], sacc[t8][1]));
            mx1 = fmaxf(mx1, fmaxf(sacc[t8][2], sacc[t8][3]));
        }
        mx0 = fmaxf(mx0, __shfl_xor_sync(0xffffffffu, mx0, 1));
        mx0 = fmaxf(mx0, __shfl_xor_sync(0xffffffffu, mx0, 2));
        mx1 = fmaxf(mx1, __shfl_xor_sync(0xffffffffu, mx1, 1));
        mx1 = fmaxf(mx1, __shfl_xor_sync(0xffffffffu, mx1, 2));
        float nm0 = fmaxf(mrow0, mx0), nm1 = fmaxf(mrow1, mx1);
        float corr0 = __expf(mrow0 - nm0), corr1 = __expf(mrow1 - nm1);
        float rs0 = 0.f, rs1 = 0.f;
        uint32_t pp0[8], pp1[8];
#pragma unroll
        for (int t8 = 0; t8 < 8; t8++) {
            float p0 = __expf(sacc[t8][0] - nm0);
            float p1 = __expf(sacc[t8][1] - nm0);
            float p2 = __expf(sacc[t8][2] - nm1);
            float p3 = __expf(sacc[t8][3] - nm1);
            rs0 += p0 + p1; rs1 += p2 + p3;
            pp0[t8] = packbf(p0, p1);
            pp1[t8] = packbf(p2, p3);
        }
        rs0 += __shfl_xor_sync(0xffffffffu, rs0, 1);
        rs0 += __shfl_xor_sync(0xffffffffu, rs0, 2);
        rs1 += __shfl_xor_sync(0xffffffffu, rs1, 1);
        rs1 += __shfl_xor_sync(0xffffffffu, rs1, 2);
        lsum0 = lsum0 * corr0 + rs0;
        lsum1 = lsum1 * corr1 + rs1;
        mrow0 = nm0; mrow1 = nm1;
#pragma unroll
        for (int t8 = 0; t8 < 8; t8++) {
            o[t8][0] *= corr0; o[t8][1] *= corr0;
            o[t8][2] *= corr1; o[t8][3] *= corr1;
        }

#pragma unroll
        for (int kk = 0; kk < 4; kk++) {
            uint32_t a0 = pp0[2 * kk];
            uint32_t a1 = pp1[2 * kk];
            uint32_t a2 = pp0[2 * kk + 1];
            uint32_t a3 = pp1[2 * kk + 1];
#pragma unroll
            for (int t8 = 0; t8 < 8; t8++) {
                const uint32_t* bp = &Vts[(t8 * 8 + lr) * ST + kk * 8 + lc];
                mma_bf16(o[t8][0], o[t8][1], o[t8][2], o[t8][3],
                         a0, a1, a2, a3, bp[0], bp[4]);
            }
        }
    }

    int row0 = m0 + wrow + lr, row1 = row0 + 8;
    float* op = g_opart + (size_t)split * EB * CAP * HD;
#pragma unroll
    for (int t8 = 0; t8 < 8; t8++) {
        int col = t8 * 8 + 2 * lc;
        *(float2*)(op + ((size_t)eb * CAP + row0) * HD + col) = make_float2(o[t8][0], o[t8][1]);
        *(float2*)(op + ((size_t)eb * CAP + row1) * HD + col) = make_float2(o[t8][2], o[t8][3]);
    }
    if (lc == 0) {
        int base = split * EB * CAP + eb * CAP;
        g_pm[base + row0] = mrow0;
        g_pl[base + row0] = lsum0;
        g_pm[base + row1] = mrow1;
        g_pl[base + row1] = lsum1;
    }
}

// ================= stage 5b: combine splits -> packed bf16 ctx =================
__global__ void combine_kernel() {
    int idx = blockIdx.x * blockDim.x + threadIdx.x;
    if (idx >= EB * CAP * 16) return;
    int t = idx >> 4;
    int c4 = (idx & 15) << 2;
    float m0 = g_pm[t], m1 = g_pm[EB * CAP + t];
    float l0 = g_pl[t], l1 = g_pl[EB * CAP + t];
    float M = fmaxf(m0, m1);
    float s0 = __expf(m0 - M), s1 = __expf(m1 - M);
    float inv = 1.f / (l0 * s0 + l1 * s1);
    const float4 a = *(const float4*)(g_opart + (size_t)t * HD + c4);
    const float4 b = *(const float4*)(g_opart + (size_t)EB * CAP * HD + (size_t)t * HD + c4);
    uint2 o;
    o.x = packbf((a.x * s0 + b.x * s1) * inv, (a.y * s0 + b.y * s1) * inv);
    o.y = packbf((a.z * s0 + b.z * s1) * inv, (a.w * s0 + b.w * s1) * inv);
    *(uint2*)(g_ctxh + (size_t)t * 32 + (c4 >> 1)) = o;
}

// ================= stage 6a: out = (ctx @ Wff + bff) * w -> bf16 g_out (BF16 mma) =====
__global__ void __launch_bounds__(256) outproj_kernel(const float* __restrict__ bff) {
    constexpr int AST = 36, BST = 36;
    extern __shared__ uint32_t dsm[];
    uint32_t* As = dsm;
    uint32_t* Bs = As + 128 * AST;
    int mt = blockIdx.x, nt = blockIdx.y, eb = blockIdx.z;
    int e = eb >> 1;
    int tid = threadIdx.x;
    int lane = tid & 31, w = tid >> 5;
    int lr = lane >> 2, lc = lane & 3;
    int wm = (w & 3) * 32, wn = (w >> 2) * 64;
    int m0 = mt * 128, n0 = nt * 128;

#pragma unroll
    for (int it = 0; it < 4; it++) {
        int idx = tid + it * 256;
        int row = idx >> 3, c = idx & 7;
        cp_async16((uint32_t)__cvta_generic_to_shared(As + row * AST + c * 4),
                   g_ctxh + (size_t)(eb * CAP + m0 + row) * 32 + c * 4);
    }
#pragma unroll
    for (int it = 0; it < 4; it++) {
        int idx = tid + it * 256;
        int n = idx >> 3, c = idx & 7;
        cp_async16((uint32_t)__cvta_generic_to_shared(Bs + n * BST + c * 4),
                   g_wfft + (size_t)(e * 1024 + n0 + n) * 32 + c * 4);
    }
    cp_commit();
    cp_wait0();
    __syncthreads();

    float acc[2][8][4];
#pragma unroll
    for (int mi = 0; mi < 2; mi++)
#pragma unroll
        for (int t8 = 0; t8 < 8; t8++)
#pragma unroll
            for (int r = 0; r < 4; r++) acc[mi][t8][r] = 0.f;

#pragma unroll
    for (int kk = 0; kk < 4; kk++) {
        uint32_t a[2][4];
#pragma unroll
        for (int mi = 0; mi < 2; mi++) {
            const uint32_t* ap = &As[(wm + mi * 16 + lr) * AST + kk * 8 + lc];
            a[mi][0] = ap[0]; a[mi][1] = ap[8 * AST];
            a[mi][2] = ap[4]; a[mi][3] = ap[8 * AST + 4];
        }
#pragma unroll
        for (int t8 = 0; t8 < 8; t8++) {
            const uint32_t* bp = &Bs[(wn + t8 * 8 + lr) * BST + kk * 8 + lc];
#pragma unroll
            for (int mi = 0; mi < 2; mi++)
                mma_bf16(acc[mi][t8][0], acc[mi][t8][1], acc[mi][t8][2], acc[mi][t8][3],
                         a[mi][0], a[mi][1], a[mi][2], a[mi][3], bp[0], bp[4]);
        }
    }

#pragma unroll
    for (int mi = 0; mi < 2; mi++) {
        int row0 = m0 + wm + mi * 16 + lr;
        int row1 = row0 + 8;
        float wv0 = g_w[eb * CAP + row0];
        float wv1 = g_w[eb * CAP + row1];
#pragma unroll
        for (int t8 = 0; t8 < 8; t8++) {
            int col = n0 + wn + t8 * 8 + 2 * lc;
            float2 bf = *(const float2*)(bff + col);
            if (wv0 != 0.f) {
                __nv_bfloat162 v;
                v.x = __float2bfloat16((acc[mi][t8][0] + bf.x) * wv0);
                v.y = __float2bfloat16((acc[mi][t8][1] + bf.y) * wv0);
                *(__nv_bfloat162*)(g_out + ((size_t)eb * CAP + row0) * D + col) = v;
            }
            if (wv1 != 0.f) {
                __nv_bfloat162 v;
                v.x = __float2bfloat16((acc[mi][t8][2] + bf.x) * wv1);
                v.y = __float2bfloat16((acc[mi][t8][3] + bf.y) * wv1);
                *(__nv_bfloat162*)(g_out + ((size_t)eb * CAP + row1) * D + col) = v;
            }
        }
    }
}

// ================= stage 6b: gather-combine + residual + LayerNorm =================
__global__ void ln_kernel(const float* __restrict__ x,
                          const float* __restrict__ gamma,
                          const float* __restrict__ beta,
                          float* __restrict__ out) {
    int token = blockIdx.x;
    int b = token >> 11;
    int tid = threadIdx.x;
    __shared__ int sh_base[E];
    __shared__ float red[8];
    if (tid < E) {
        int p = g_inv[tid * NTOK + token];
        int base = -1;
        if (p >= 0) {
            int idx = (tid * B + b) * CAP + p;
            if (g_w[idx] != 0.f) base = idx;
        }
        sh_base[tid] = base;
    }
    __syncthreads();
    float4 c = make_float4(0.f, 0.f, 0.f, 0.f);
#pragma unroll
    for (int e = 0; e < E; e++) {
        int base = sh_base[e];
        if (base >= 0) {
            uint2 u = *(const uint2*)(g_out + (size_t)base * D + tid * 4);
            __nv_bfloat162 p0 = *reinterpret_cast<__nv_bfloat162*>(&u.x);
            __nv_bfloat162 p1 = *reinterpret_cast<__nv_bfloat162*>(&u.y);
            c.x += __bfloat162float(p0.x); c.y += __bfloat162float(p0.y);
            c.z += __bfloat162float(p1.x); c.w += __bfloat162float(p1.y);
        }
    }
    float4 x4 = *(const float4*)(x + (size_t)token * D + tid * 4);
    float h[4] = {x4.x + c.x, x4.y + c.y, x4.z + c.z, x4.w + c.w};
    float s = h[0] + h[1] + h[2] + h[3];
#pragma unroll
    for (int off = 16; off > 0; off >>= 1) s += __shfl_xor_sync(0xffffffffu, s, off);
    int warp = tid >> 5, lane = tid & 31;
    if (lane == 0) red[warp] = s;
    __syncthreads();
    float total = 0.f;
#pragma unroll
    for (int w = 0; w < 8; w++) total += red[w];
    __syncthreads();
    float mu = total * (1.0f / D);
    float ss = 0.f;
#pragma unroll
    for (int t = 0; t < 4; t++) {
        float dlt = h[t] - mu;
        ss += dlt * dlt;
    }
#pragma unroll
    for (int off = 16; off > 0; off >>= 1) ss += __shfl_xor_sync(0xffffffffu, ss, off);
    if (lane == 0) red[warp] = ss;
    __syncthreads();
    float vtot = 0.f;
#pragma unroll
    for (int w = 0; w < 8; w++) vtot += red[w];
    float var = vtot * (1.0f / D);
    float inv = rsqrtf(var + 1e-5f);
    float4 g4 = *(const float4*)(gamma + tid * 4);
    float4 be4 = *(const float4*)(beta + tid * 4);
    float4 o4;
    o4.x = (h[0] - mu) * inv * g4.x + be4.x;
    o4.y = (h[1] - mu) * inv * g4.y + be4.y;
    o4.z = (h[2] - mu) * inv * g4.z + be4.z;
    o4.w = (h[3] - mu) * inv * g4.w + be4.w;
    *(float4*)(out + (size_t)token * D + tid * 4) = o4;
}

// ================= launch =================
extern "C" void kernel_launch(void* const* d_in, const int* in_sizes, int n_in,
                              void* d_out, int out_size) {
    const float* x     = (const float*)d_in[0];
    const float* wg    = (const float*)d_in[1];
    const float* bg    = (const float*)d_in[2];
    const float* Wq    = (const float*)d_in[3];
    const float* Wkv   = (const float*)d_in[4];
    const float* Wff   = (const float*)d_in[5];
    const float* bff   = (const float*)d_in[6];
    const float* gamma = (const float*)d_in[7];
    const float* beta  = (const float*)d_in[8];
    float* out = (float*)d_out;

    (void)in_sizes; (void)n_in; (void)out_size;

    wgt_kernel<<<E * D / 256, 256>>>(wg);
    fat_kernel<<<3840, 256>>>(x, bg, Wq, Wkv, Wff);

    mask_kernel<<<dim3(EB, 8), 256>>>();
    select_kernel<<<dim3(EB, 8), 256>>>();

    int proj_smem = 2 * (64 * 36 + 192 * 36) * (int)sizeof(uint32_t);  // 73,728 B
    cudaFuncSetAttribute(proj_kernel, cudaFuncAttributeMaxDynamicSharedMemorySize, proj_smem);
    proj_kernel<<<dim3(CAP / 64, EB), 256, proj_smem>>>();

    rope_kernel<<<(EB * CAP * 16 + 255) / 256, 256>>>();

    int attn_smem = 384 * 36 * (int)sizeof(uint32_t);   // 55,296 B
    cudaFuncSetAttribute(attn_kernel, cudaFuncAttributeMaxDynamicSharedMemorySize, attn_smem);
    attn_kernel<<<dim3(CAP / 128, EB, 2), 256, attn_smem>>>();

    combine_kernel<<<(EB * CAP * 16 + 255) / 256, 256>>>();

    int op_smem = 2 * 128 * 36 * (int)sizeof(uint32_t);  // 36,864 B
    cudaFuncSetAttribute(outproj_kernel, cudaFuncAttributeMaxDynamicSharedMemorySize, op_smem);
    outproj_kernel<<<dim3(CAP / 128, D / 128, EB), 256, op_smem>>>(bff);

    ln_kernel<<<NTOK, 256>>>(x, gamma, beta, out);
}